// round 16
// baseline (speedup 1.0000x reference)
#include <cuda_runtime.h>
#include <math.h>

#define B_ 16
#define N_ 2048
#define S0_ 256
#define S1_ 128
#define K_ 32
#define EPS_ 1e-5f

// ------------------- scratch (static device globals) ------------------------
__device__ float g_coords[B_*N_*3];
__device__ float g_h[B_*N_*64];         // stage1 raw h, then stage2 raw h (in-place)
__device__ float g_P[B_*N_*128];        // P0 [32768,128]; reused P1 [4096,256]
__device__ float g_tc[B_*S0_*128];      // tc0 [4096,128]; reused tc1 [2048,256]
__device__ float g_f1[B_*S0_*128];
__device__ float g_xyz1[B_*S0_*3];
__device__ float g_xyz2[B_*S1_*3];
__device__ int   g_fps0[B_*S0_];
__device__ int   g_fps1[B_*S1_];
__device__ int   g_knn0[B_*S0_*K_];
__device__ int   g_knn1[B_*S1_*K_];
__device__ float g_w2t[64*64];
__device__ float g_wl0t[64*128];
__device__ float g_wd0t[64*128];
__device__ float g_wl1t[128*256];
__device__ float g_wd1t[128*256];
__device__ float g_hmax[B_*S0_*128];    // also fits B_*S1_*256
__device__ float g_hmin[B_*S0_*128];
__device__ float g_stats[1024];

// ------------------- shared-memory role structs ------------------------------
struct GemmS {
    float sA[64][68];
    float sW[64][68];
    int   sG[64];
    float sSum[64], sSq[64];
    float sSc[128], sSb[128];
};
struct FpsS {
    float cx[N_], cy[N_], cz[N_];
    float cent[3];
    float wv[8];
    int   wi[8];
};
struct KnnS {
    float q[3];
    float wv[8];
    int   wi[8];
    int   win;
};
struct GroupS { int idx[2][K_]; };

union Ph2U { GemmS g; FpsS f; };
union Ph3U { GemmS g; FpsS f; KnnS k; };
union Ph4U { KnnS k; GroupS grp; };

// ------------------- weight prep ---------------------------------------------
__global__ void k_prepwA(const float* __restrict__ w2) {
    int i = blockIdx.x * 256 + threadIdx.x;
    if (i < 1024) { g_stats[i] = 0.f; return; }
    i -= 1024;
    if (i < 4096) { int d = i >> 6, o = i & 63; g_w2t[i] = w2[o*64 + d]; }
}

__global__ void k_prepwB(const float* __restrict__ wsg0, const float* __restrict__ wsg1) {
    int i = blockIdx.x * 256 + threadIdx.x;
    if (i < 8192)  { int d = i >> 7, o = i & 127; g_wl0t[i] = wsg0[o*128 + d]; return; }
    i -= 8192;
    if (i < 8192)  { int d = i >> 7, o = i & 127; g_wd0t[i] = wsg0[o*128 + 64 + d] - wsg0[o*128 + d]; return; }
    i -= 8192;
    if (i < 32768) { int d = i >> 8, o = i & 255; g_wl1t[i] = wsg1[o*256 + d]; return; }
    i -= 32768;
    if (i < 32768) { int d = i >> 8, o = i & 255; g_wd1t[i] = wsg1[o*256 + 128 + d] - wsg1[o*256 + d]; }
}

// ------------------- stage 1: transpose + 3->64 matvec + stats ---------------
__global__ void k_stage1(const float* __restrict__ x, const float* __restrict__ w1) {
    __shared__ float s_w[192];
    __shared__ float s_red[256];
    int t = threadIdx.x;
    if (t < 192) s_w[t] = w1[t];
    int j = t >> 6, o = t & 63;
    float ls = 0.f, lq = 0.f;
    __syncthreads();
    #pragma unroll
    for (int it = 0; it < 8; it++) {
        int p = blockIdx.x * 32 + it * 4 + j;
        int b = p >> 11, n = p & (N_ - 1);
        float cx = x[(b*3 + 0)*N_ + n];   // 64 threads same addr -> broadcast
        float cy = x[(b*3 + 1)*N_ + n];
        float cz = x[(b*3 + 2)*N_ + n];
        if (o == 0) g_coords[p*3]     = cx;
        if (o == 1) g_coords[p*3 + 1] = cy;
        if (o == 2) g_coords[p*3 + 2] = cz;
        float h = s_w[o*3]*cx + s_w[o*3+1]*cy + s_w[o*3+2]*cz;
        g_h[p*64 + o] = h;
        ls += h; lq += h*h;
    }
    s_red[t] = ls; __syncthreads();
    if (t < 64) atomicAdd(&g_stats[t], s_red[t]+s_red[64+t]+s_red[128+t]+s_red[192+t]);
    __syncthreads();
    s_red[t] = lq; __syncthreads();
    if (t < 64) atomicAdd(&g_stats[64+t], s_red[t]+s_red[64+t]+s_red[128+t]+s_red[192+t]);
}

// ------------------- GEMM device function (fused input-BN+ReLU) --------------
__device__ __forceinline__ void dev_gemm(
    GemmS& sh, int bx, int by, const float* __restrict__ A,
    const float* __restrict__ Wt, float* __restrict__ out,
    const int* __restrict__ idx, int D, int O, int normOff,
    const float* __restrict__ gamma, const float* __restrict__ beta, int statsOff)
{
    int t = threadIdx.x;
    int r0 = bx * 64, c0 = by * 64;
    if (t < 64) { sh.sG[t] = idx ? idx[r0 + t] : (r0 + t); sh.sSum[t] = 0.f; sh.sSq[t] = 0.f; }
    if (normOff >= 0 && t < D) {
        const float inv = 1.f / 32768.f;
        float m  = g_stats[normOff + t] * inv;
        float v  = g_stats[normOff + D + t] * inv - m*m;
        float sc = gamma[t] * rsqrtf(v + EPS_);
        sh.sSc[t] = sc; sh.sSb[t] = beta[t] - m * sc;
    }
    __syncthreads();

    float acc[4][4];
    #pragma unroll
    for (int rr = 0; rr < 4; rr++)
        #pragma unroll
        for (int cc = 0; cc < 4; cc++) acc[rr][cc] = 0.f;

    int tr = t >> 4, tcx = t & 15;

    for (int d0 = 0; d0 < D; d0 += 64) {
        for (int e = t; e < 4096; e += 256) {
            int r = e >> 6, d = e & 63;
            float v = A[sh.sG[r]*D + d0 + d];
            if (normOff >= 0) v = fmaxf(0.f, fmaf(v, sh.sSc[d0 + d], sh.sSb[d0 + d]));
            sh.sA[r][d] = v;
            sh.sW[r][d] = Wt[(d0 + r)*O + c0 + d];
        }
        __syncthreads();
        #pragma unroll 8
        for (int dd = 0; dd < 64; dd++) {
            float av[4], bv[4];
            #pragma unroll
            for (int rr = 0; rr < 4; rr++) av[rr] = sh.sA[tr*4 + rr][dd];
            #pragma unroll
            for (int cc = 0; cc < 4; cc++) bv[cc] = sh.sW[dd][tcx*4 + cc];
            #pragma unroll
            for (int rr = 0; rr < 4; rr++)
                #pragma unroll
                for (int cc = 0; cc < 4; cc++) acc[rr][cc] += av[rr] * bv[cc];
        }
        __syncthreads();
    }

    #pragma unroll
    for (int rr = 0; rr < 4; rr++) {
        int r = r0 + tr*4 + rr;
        #pragma unroll
        for (int cc = 0; cc < 4; cc++) out[r*O + c0 + tcx*4 + cc] = acc[rr][cc];
    }

    if (statsOff >= 0) {
        #pragma unroll
        for (int cc = 0; cc < 4; cc++) {
            float s = acc[0][cc] + acc[1][cc] + acc[2][cc] + acc[3][cc];
            float q = acc[0][cc]*acc[0][cc] + acc[1][cc]*acc[1][cc]
                    + acc[2][cc]*acc[2][cc] + acc[3][cc]*acc[3][cc];
            atomicAdd(&sh.sSum[tcx*4 + cc], s);
            atomicAdd(&sh.sSq[tcx*4 + cc], q);
        }
        __syncthreads();
        if (t < 64) {
            atomicAdd(&g_stats[statsOff + c0 + t], sh.sSum[t]);
            atomicAdd(&g_stats[statsOff + O + c0 + t], sh.sSq[t]);
        }
    }
}

// ------------------- FPS device function (256 threads) -----------------------
template<int NPTS, int S, int P>
__device__ __forceinline__ void dev_fps(FpsS& sh, int b,
    const float* __restrict__ coords, int* __restrict__ fpsIdx, float* __restrict__ xyzOut)
{
    int t = threadIdx.x, w = t >> 5, lane = t & 31;

    float px[P], py[P], pz[P], pd[P];
    #pragma unroll
    for (int p = 0; p < P; p++) {
        int n = t*P + p;
        px[p] = coords[(b*NPTS + n)*3];
        py[p] = coords[(b*NPTS + n)*3 + 1];
        pz[p] = coords[(b*NPTS + n)*3 + 2];
        sh.cx[n] = px[p]; sh.cy[n] = py[p]; sh.cz[n] = pz[p];
        pd[p] = 1e10f;
    }
    if (t == 0) {
        fpsIdx[b*S] = b*NPTS;
        xyzOut[b*S*3]     = px[0];
        xyzOut[b*S*3 + 1] = py[0];
        xyzOut[b*S*3 + 2] = pz[0];
        sh.cent[0] = px[0]; sh.cent[1] = py[0]; sh.cent[2] = pz[0];
    }
    __syncthreads();

    for (int i = 1; i < S; i++) {
        float cx = sh.cent[0], cy = sh.cent[1], cz = sh.cent[2];
        float bv = -1e30f; int bi = 0x7fffffff;
        #pragma unroll
        for (int p = 0; p < P; p++) {
            float dx = px[p]-cx, dy = py[p]-cy, dz = pz[p]-cz;
            float d = fminf(pd[p], dx*dx + dy*dy + dz*dz);
            pd[p] = d;
            if (d > bv) { bv = d; bi = t*P + p; }
        }
        #pragma unroll
        for (int off = 16; off; off >>= 1) {
            float ov = __shfl_down_sync(0xffffffffu, bv, off);
            int   oi = __shfl_down_sync(0xffffffffu, bi, off);
            if (ov > bv || (ov == bv && oi < bi)) { bv = ov; bi = oi; }
        }
        if (lane == 0) { sh.wv[w] = bv; sh.wi[w] = bi; }
        __syncthreads();
        if (w == 0) {
            bv = (lane < 8) ? sh.wv[lane] : -1e30f;
            bi = (lane < 8) ? sh.wi[lane] : 0x7fffffff;
            #pragma unroll
            for (int off = 4; off; off >>= 1) {
                float ov = __shfl_down_sync(0xffffffffu, bv, off);
                int   oi = __shfl_down_sync(0xffffffffu, bi, off);
                if (ov > bv || (ov == bv && oi < bi)) { bv = ov; bi = oi; }
            }
            if (lane == 0) {
                fpsIdx[b*S + i] = b*NPTS + bi;
                float wx = sh.cx[bi], wy = sh.cy[bi], wz = sh.cz[bi];
                xyzOut[(b*S + i)*3]     = wx;
                xyzOut[(b*S + i)*3 + 1] = wy;
                xyzOut[(b*S + i)*3 + 2] = wz;
                sh.cent[0] = wx; sh.cent[1] = wy; sh.cent[2] = wz;
            }
        }
        __syncthreads();
    }
}

// ------------------- kNN device function (256 threads) -----------------------
template<int NPTS, int S, int P>
__device__ __forceinline__ void dev_knn(KnnS& sh, int bs,
    const float* __restrict__ query, const float* __restrict__ coords, int* __restrict__ knn)
{
    int t = threadIdx.x, w = t >> 5, lane = t & 31;
    int b = bs / S;
    if (t < 3) sh.q[t] = query[bs*3 + t];
    __syncthreads();

    int base = b*NPTS;
    float pd[P];
    #pragma unroll
    for (int p = 0; p < P; p++) {
        int n = t*P + p;
        float dx = coords[(base+n)*3]   - sh.q[0];
        float dy = coords[(base+n)*3+1] - sh.q[1];
        float dz = coords[(base+n)*3+2] - sh.q[2];
        pd[p] = dx*dx + dy*dy + dz*dz;
    }

    for (int i = 0; i < K_; i++) {
        float bv = 1e30f; int bi = 0x7fffffff;
        #pragma unroll
        for (int p = 0; p < P; p++) {
            if (pd[p] < bv) { bv = pd[p]; bi = t*P + p; }
        }
        #pragma unroll
        for (int off = 16; off; off >>= 1) {
            float ov = __shfl_down_sync(0xffffffffu, bv, off);
            int   oi = __shfl_down_sync(0xffffffffu, bi, off);
            if (ov < bv || (ov == bv && oi < bi)) { bv = ov; bi = oi; }
        }
        if (lane == 0) { sh.wv[w] = bv; sh.wi[w] = bi; }
        __syncthreads();
        if (w == 0) {
            bv = (lane < 8) ? sh.wv[lane] : 1e30f;
            bi = (lane < 8) ? sh.wi[lane] : 0x7fffffff;
            #pragma unroll
            for (int off = 4; off; off >>= 1) {
                float ov = __shfl_down_sync(0xffffffffu, bv, off);
                int   oi = __shfl_down_sync(0xffffffffu, bi, off);
                if (ov < bv || (ov == bv && oi < bi)) { bv = ov; bi = oi; }
            }
            if (lane == 0) { knn[bs*K_ + i] = base + bi; sh.win = bi; }
        }
        __syncthreads();
        int win = sh.win;
        #pragma unroll
        for (int p = 0; p < P; p++)
            if (win == t*P + p) pd[p] = 1e30f;
        __syncthreads();
    }
}

// ------------------- phase kernels -------------------------------------------
__global__ void k_nop() {}

// phase2: FPS0 (blocks 0..15) || stage2 GEMM (blocks 16..527)
__global__ void __launch_bounds__(256) k_phase2(const float* __restrict__ g1,
                                                const float* __restrict__ b1) {
    __shared__ Ph2U sh;
    if (blockIdx.x < 16)
        dev_fps<N_, S0_, 8>(sh.f, blockIdx.x, g_coords, g_fps0, g_xyz1);
    else
        dev_gemm(sh.g, blockIdx.x - 16, 0, g_h, g_w2t, g_h, 0, 64, 64, 0, g1, b1, 128);
}

// phase3: FPS1 [0,16) || P0 GEMM [16,1040) || tc0 GEMM [1040,1168) || kNN0 [1168,5264)
__global__ void __launch_bounds__(256) k_phase3(const float* __restrict__ g2,
                                                const float* __restrict__ b2) {
    __shared__ Ph3U sh;
    int bi = blockIdx.x;
    if (bi < 16) {
        dev_fps<S0_, S1_, 1>(sh.f, bi, g_xyz1, g_fps1, g_xyz2);
    } else if (bi < 1040) {
        int i = bi - 16;
        dev_gemm(sh.g, i & 511, i >> 9, g_h, g_wl0t, g_P, 0, 64, 128, 128, g2, b2, -1);
    } else if (bi < 1168) {
        int i = bi - 1040;
        dev_gemm(sh.g, i & 63, i >> 6, g_h, g_wd0t, g_tc, g_fps0, 64, 128, 128, g2, b2, -1);
    } else {
        dev_knn<N_, S0_, 8>(sh.k, bi - 1168, g_xyz1, g_coords, g_knn0);
    }
}

// phase4: kNN1 [0,2048) || group0 [2048,4096) (2 centroids per block)
__global__ void __launch_bounds__(256) k_phase4() {
    __shared__ Ph4U sh;
    int bi = blockIdx.x;
    if (bi < 2048) {
        dev_knn<S0_, S1_, 1>(sh.k, bi, g_xyz2, g_xyz1, g_knn1);
    } else {
        int blk = bi - 2048;
        int t = threadIdx.x;
        int half = t >> 7, o = t & 127;
        int bs = blk*2 + half;
        if (o < K_) sh.grp.idx[half][o] = g_knn0[bs*K_ + o];
        __syncthreads();
        float tcv = g_tc[bs*128 + o];
        float s = 0.f, q = 0.f, mx = -1e30f, mn = 1e30f;
        #pragma unroll 8
        for (int k = 0; k < K_; k++) {
            float v = g_P[sh.grp.idx[half][k]*128 + o] + tcv;
            s += v; q += v*v; mx = fmaxf(mx, v); mn = fminf(mn, v);
        }
        g_hmax[bs*128 + o] = mx;
        g_hmin[bs*128 + o] = mn;
        atomicAdd(&g_stats[256 + o], s);
        atomicAdd(&g_stats[256 + 128 + o], q);
    }
}

// phase6: P1 GEMM [0,256) || tc1 GEMM [256,384)
__global__ void __launch_bounds__(256) k_phase6() {
    __shared__ GemmS sh;
    int bi = blockIdx.x;
    if (bi < 256)
        dev_gemm(sh, bi & 63, bi >> 6, g_f1, g_wl1t, g_P, 0, 128, 256, -1, 0, 0, -1);
    else {
        int i = bi - 256;
        dev_gemm(sh, i & 31, i >> 5, g_f1, g_wd1t, g_tc, g_fps1, 128, 256, -1, 0, 0, -1);
    }
}

// group1: O=256, 1 centroid per block
__global__ void k_group1() {
    __shared__ int sidx[K_];
    int bs = blockIdx.x, o = threadIdx.x;
    if (o < K_) sidx[o] = g_knn1[bs*K_ + o];
    __syncthreads();
    float tcv = g_tc[bs*256 + o];
    float s = 0.f, q = 0.f, mx = -1e30f, mn = 1e30f;
    #pragma unroll 8
    for (int k = 0; k < K_; k++) {
        float v = g_P[sidx[k]*256 + o] + tcv;
        s += v; q += v*v; mx = fmaxf(mx, v); mn = fminf(mn, v);
    }
    g_hmax[bs*256 + o] = mx;
    g_hmin[bs*256 + o] = mn;
    atomicAdd(&g_stats[512 + o], s);
    atomicAdd(&g_stats[512 + 256 + o], q);
}

// finalize: BN + ReLU + (monotone) max over k
__global__ void k_finalize(const float* __restrict__ gamma, const float* __restrict__ beta,
                           int statsOff, int O, int S, float inv,
                           float* __restrict__ outp, int transposed) {
    int i = blockIdx.x * 256 + threadIdx.x;
    int o = i & (O - 1);
    float m   = g_stats[statsOff + o] * inv;
    float var = g_stats[statsOff + O + o] * inv - m*m;
    float sc  = gamma[o] * rsqrtf(var + EPS_);
    float h   = (sc >= 0.f) ? g_hmax[i] : g_hmin[i];
    float v   = fmaxf(0.f, (h - m) * sc + beta[o]);
    if (transposed) {
        int bs = i / O;
        int b = bs / S, ss = bs - b*S;
        outp[(b*O + o)*S + ss] = v;
    } else {
        g_f1[i] = v;
    }
}

// ------------------- launch ---------------------------------------------------
extern "C" void kernel_launch(void* const* d_in, const int* in_sizes, int n_in,
                              void* d_out, int out_size) {
    (void)in_sizes; (void)n_in; (void)out_size;
    const float* x    = (const float*)d_in[0];
    const float* w1   = (const float*)d_in[1];
    const float* g1   = (const float*)d_in[2];
    const float* b1   = (const float*)d_in[3];
    const float* w2   = (const float*)d_in[4];
    const float* g2   = (const float*)d_in[5];
    const float* b2   = (const float*)d_in[6];
    const float* wsg0 = (const float*)d_in[7];
    const float* gsg0 = (const float*)d_in[8];
    const float* bsg0 = (const float*)d_in[9];
    const float* wsg1 = (const float*)d_in[10];
    const float* gsg1 = (const float*)d_in[11];
    const float* bsg1 = (const float*)d_in[12];
    float* out = (float*)d_out;

    k_prepwA<<<20, 256>>>(w2);                                         // 1
    k_prepwB<<<320, 256>>>(wsg0, wsg1);                                // 2
    k_stage1<<<1024, 256>>>(x, w1);                                    // 3
    k_phase2<<<528, 256>>>(g1, b1);                                    // 4: fps0 || stage2 gemm
    k_nop<<<1, 32>>>();                                                // 5: shift ncu slot
    k_phase3<<<5264, 256>>>(g2, b2);                                   // 6: fps1 || P0 || tc0 || knn0 (profiled)
    k_phase4<<<4096, 256>>>();                                         // 7: knn1 || group0
    k_finalize<<<2048, 256>>>(gsg0, bsg0, 256, 128, S0_, 1.f/131072.f, out, 0);  // 8 -> f1
    k_phase6<<<384, 256>>>();                                          // 9: P1 || tc1
    k_group1<<<2048, 256>>>();                                         // 10
    k_finalize<<<2048, 256>>>(gsg1, bsg1, 512, 256, S1_, 1.f/65536.f, out, 1);   // 11
}

// round 17
// speedup vs baseline: 1.0039x; 1.0039x over previous
#include <cuda_runtime.h>
#include <math.h>

#define B_ 16
#define N_ 2048
#define S0_ 256
#define S1_ 128
#define K_ 32
#define EPS_ 1e-5f

// ------------------- scratch (static device globals) ------------------------
__device__ float g_coords[B_*N_*3];
__device__ float g_h[B_*N_*64];         // stage1 raw h, then stage2 raw h (in-place)
__device__ float g_P[B_*N_*128];        // P0 [32768,128]; reused P1 [4096,256]
__device__ float g_tc[B_*S0_*128];      // tc0 [4096,128]; reused tc1 [2048,256]
__device__ float g_f1[B_*S0_*128];
__device__ float g_xyz1[B_*S0_*3];
__device__ float g_xyz2[B_*S1_*3];
__device__ int   g_fps0[B_*S0_];
__device__ int   g_fps1[B_*S1_];
__device__ int   g_knn0[B_*S0_*K_];
__device__ int   g_knn1[B_*S1_*K_];
__device__ float g_w2t[64*64];
__device__ float g_wl0t[64*128];
__device__ float g_wd0t[64*128];
__device__ float g_wl1t[128*256];
__device__ float g_wd1t[128*256];
__device__ float g_hmax[B_*S0_*128];    // also fits B_*S1_*256
__device__ float g_hmin[B_*S0_*128];
__device__ float g_stats[1024];

// ------------------- shared-memory role structs ------------------------------
struct GemmS {
    float sA[64][68];
    float sW[64][68];
    int   sG[64];
    float sSum[64], sSq[64];
    float sSc[128], sSb[128];
};
struct FpsS {
    float cx[N_], cy[N_], cz[N_];
    float cent[3];
    float wv[8];
    int   wi[8];
};
struct KnnS {
    float q[3];
    float wv[8];
    int   wi[8];
    int   win;
};
struct GroupS { int idx[2][K_]; };

union Ph2U { GemmS g; FpsS f; };
union Ph3U { GemmS g; FpsS f; KnnS k; };
union Ph4U { KnnS k; GroupS grp; };

// ------------------- weight prep ---------------------------------------------
__global__ void k_prepwA(const float* __restrict__ w2) {
    int i = blockIdx.x * 256 + threadIdx.x;
    if (i < 1024) { g_stats[i] = 0.f; return; }
    i -= 1024;
    if (i < 4096) { int d = i >> 6, o = i & 63; g_w2t[i] = w2[o*64 + d]; }
}

__global__ void k_prepwB(const float* __restrict__ wsg0, const float* __restrict__ wsg1) {
    int i = blockIdx.x * 256 + threadIdx.x;
    if (i < 8192)  { int d = i >> 7, o = i & 127; g_wl0t[i] = wsg0[o*128 + d]; return; }
    i -= 8192;
    if (i < 8192)  { int d = i >> 7, o = i & 127; g_wd0t[i] = wsg0[o*128 + 64 + d] - wsg0[o*128 + d]; return; }
    i -= 8192;
    if (i < 32768) { int d = i >> 8, o = i & 255; g_wl1t[i] = wsg1[o*256 + d]; return; }
    i -= 32768;
    if (i < 32768) { int d = i >> 8, o = i & 255; g_wd1t[i] = wsg1[o*256 + 128 + d] - wsg1[o*256 + d]; }
}

// ------------------- stage 1: transpose + 3->64 matvec + stats ---------------
__global__ void k_stage1(const float* __restrict__ x, const float* __restrict__ w1) {
    __shared__ float s_w[192];
    __shared__ float s_red[256];
    int t = threadIdx.x;
    if (t < 192) s_w[t] = w1[t];
    int j = t >> 6, o = t & 63;
    float ls = 0.f, lq = 0.f;
    __syncthreads();
    #pragma unroll
    for (int it = 0; it < 8; it++) {
        int p = blockIdx.x * 32 + it * 4 + j;
        int b = p >> 11, n = p & (N_ - 1);
        float cx = x[(b*3 + 0)*N_ + n];   // 64 threads same addr -> broadcast
        float cy = x[(b*3 + 1)*N_ + n];
        float cz = x[(b*3 + 2)*N_ + n];
        if (o == 0) g_coords[p*3]     = cx;
        if (o == 1) g_coords[p*3 + 1] = cy;
        if (o == 2) g_coords[p*3 + 2] = cz;
        float h = s_w[o*3]*cx + s_w[o*3+1]*cy + s_w[o*3+2]*cz;
        g_h[p*64 + o] = h;
        ls += h; lq += h*h;
    }
    s_red[t] = ls; __syncthreads();
    if (t < 64) atomicAdd(&g_stats[t], s_red[t]+s_red[64+t]+s_red[128+t]+s_red[192+t]);
    __syncthreads();
    s_red[t] = lq; __syncthreads();
    if (t < 64) atomicAdd(&g_stats[64+t], s_red[t]+s_red[64+t]+s_red[128+t]+s_red[192+t]);
}

// ------------------- GEMM device function (fused input-BN+ReLU) --------------
__device__ __forceinline__ void dev_gemm(
    GemmS& sh, int bx, int by, const float* __restrict__ A,
    const float* __restrict__ Wt, float* __restrict__ out,
    const int* __restrict__ idx, int D, int O, int normOff,
    const float* __restrict__ gamma, const float* __restrict__ beta, int statsOff)
{
    int t = threadIdx.x;
    int r0 = bx * 64, c0 = by * 64;
    if (t < 64) { sh.sG[t] = idx ? idx[r0 + t] : (r0 + t); sh.sSum[t] = 0.f; sh.sSq[t] = 0.f; }
    if (normOff >= 0 && t < D) {
        const float inv = 1.f / 32768.f;
        float m  = g_stats[normOff + t] * inv;
        float v  = g_stats[normOff + D + t] * inv - m*m;
        float sc = gamma[t] * rsqrtf(v + EPS_);
        sh.sSc[t] = sc; sh.sSb[t] = beta[t] - m * sc;
    }
    __syncthreads();

    float acc[4][4];
    #pragma unroll
    for (int rr = 0; rr < 4; rr++)
        #pragma unroll
        for (int cc = 0; cc < 4; cc++) acc[rr][cc] = 0.f;

    int tr = t >> 4, tcx = t & 15;

    for (int d0 = 0; d0 < D; d0 += 64) {
        for (int e = t; e < 4096; e += 256) {
            int r = e >> 6, d = e & 63;
            float v = A[sh.sG[r]*D + d0 + d];
            if (normOff >= 0) v = fmaxf(0.f, fmaf(v, sh.sSc[d0 + d], sh.sSb[d0 + d]));
            sh.sA[r][d] = v;
            sh.sW[r][d] = Wt[(d0 + r)*O + c0 + d];
        }
        __syncthreads();
        #pragma unroll 8
        for (int dd = 0; dd < 64; dd++) {
            float av[4], bv[4];
            #pragma unroll
            for (int rr = 0; rr < 4; rr++) av[rr] = sh.sA[tr*4 + rr][dd];
            #pragma unroll
            for (int cc = 0; cc < 4; cc++) bv[cc] = sh.sW[dd][tcx*4 + cc];
            #pragma unroll
            for (int rr = 0; rr < 4; rr++)
                #pragma unroll
                for (int cc = 0; cc < 4; cc++) acc[rr][cc] += av[rr] * bv[cc];
        }
        __syncthreads();
    }

    #pragma unroll
    for (int rr = 0; rr < 4; rr++) {
        int r = r0 + tr*4 + rr;
        #pragma unroll
        for (int cc = 0; cc < 4; cc++) out[r*O + c0 + tcx*4 + cc] = acc[rr][cc];
    }

    if (statsOff >= 0) {
        #pragma unroll
        for (int cc = 0; cc < 4; cc++) {
            float s = acc[0][cc] + acc[1][cc] + acc[2][cc] + acc[3][cc];
            float q = acc[0][cc]*acc[0][cc] + acc[1][cc]*acc[1][cc]
                    + acc[2][cc]*acc[2][cc] + acc[3][cc]*acc[3][cc];
            atomicAdd(&sh.sSum[tcx*4 + cc], s);
            atomicAdd(&sh.sSq[tcx*4 + cc], q);
        }
        __syncthreads();
        if (t < 64) {
            atomicAdd(&g_stats[statsOff + c0 + t], sh.sSum[t]);
            atomicAdd(&g_stats[statsOff + O + c0 + t], sh.sSq[t]);
        }
    }
}

// ------------------- FPS device function (256 threads) -----------------------
template<int NPTS, int S, int P>
__device__ __forceinline__ void dev_fps(FpsS& sh, int b,
    const float* __restrict__ coords, int* __restrict__ fpsIdx, float* __restrict__ xyzOut)
{
    int t = threadIdx.x, w = t >> 5, lane = t & 31;

    float px[P], py[P], pz[P], pd[P];
    #pragma unroll
    for (int p = 0; p < P; p++) {
        int n = t*P + p;
        px[p] = coords[(b*NPTS + n)*3];
        py[p] = coords[(b*NPTS + n)*3 + 1];
        pz[p] = coords[(b*NPTS + n)*3 + 2];
        sh.cx[n] = px[p]; sh.cy[n] = py[p]; sh.cz[n] = pz[p];
        pd[p] = 1e10f;
    }
    if (t == 0) {
        fpsIdx[b*S] = b*NPTS;
        xyzOut[b*S*3]     = px[0];
        xyzOut[b*S*3 + 1] = py[0];
        xyzOut[b*S*3 + 2] = pz[0];
        sh.cent[0] = px[0]; sh.cent[1] = py[0]; sh.cent[2] = pz[0];
    }
    __syncthreads();

    for (int i = 1; i < S; i++) {
        float cx = sh.cent[0], cy = sh.cent[1], cz = sh.cent[2];
        float bv = -1e30f; int bi = 0x7fffffff;
        #pragma unroll
        for (int p = 0; p < P; p++) {
            float dx = px[p]-cx, dy = py[p]-cy, dz = pz[p]-cz;
            float d = fminf(pd[p], dx*dx + dy*dy + dz*dz);
            pd[p] = d;
            if (d > bv) { bv = d; bi = t*P + p; }
        }
        #pragma unroll
        for (int off = 16; off; off >>= 1) {
            float ov = __shfl_down_sync(0xffffffffu, bv, off);
            int   oi = __shfl_down_sync(0xffffffffu, bi, off);
            if (ov > bv || (ov == bv && oi < bi)) { bv = ov; bi = oi; }
        }
        if (lane == 0) { sh.wv[w] = bv; sh.wi[w] = bi; }
        __syncthreads();
        if (w == 0) {
            bv = (lane < 8) ? sh.wv[lane] : -1e30f;
            bi = (lane < 8) ? sh.wi[lane] : 0x7fffffff;
            #pragma unroll
            for (int off = 4; off; off >>= 1) {
                float ov = __shfl_down_sync(0xffffffffu, bv, off);
                int   oi = __shfl_down_sync(0xffffffffu, bi, off);
                if (ov > bv || (ov == bv && oi < bi)) { bv = ov; bi = oi; }
            }
            if (lane == 0) {
                fpsIdx[b*S + i] = b*NPTS + bi;
                float wx = sh.cx[bi], wy = sh.cy[bi], wz = sh.cz[bi];
                xyzOut[(b*S + i)*3]     = wx;
                xyzOut[(b*S + i)*3 + 1] = wy;
                xyzOut[(b*S + i)*3 + 2] = wz;
                sh.cent[0] = wx; sh.cent[1] = wy; sh.cent[2] = wz;
            }
        }
        __syncthreads();
    }
}

// ------------------- kNN device function (256 threads) -----------------------
template<int NPTS, int S, int P>
__device__ __forceinline__ void dev_knn(KnnS& sh, int bs,
    const float* __restrict__ query, const float* __restrict__ coords, int* __restrict__ knn)
{
    int t = threadIdx.x, w = t >> 5, lane = t & 31;
    int b = bs / S;
    if (t < 3) sh.q[t] = query[bs*3 + t];
    __syncthreads();

    int base = b*NPTS;
    float pd[P];
    #pragma unroll
    for (int p = 0; p < P; p++) {
        int n = t*P + p;
        float dx = coords[(base+n)*3]   - sh.q[0];
        float dy = coords[(base+n)*3+1] - sh.q[1];
        float dz = coords[(base+n)*3+2] - sh.q[2];
        pd[p] = dx*dx + dy*dy + dz*dz;
    }

    for (int i = 0; i < K_; i++) {
        float bv = 1e30f; int bi = 0x7fffffff;
        #pragma unroll
        for (int p = 0; p < P; p++) {
            if (pd[p] < bv) { bv = pd[p]; bi = t*P + p; }
        }
        #pragma unroll
        for (int off = 16; off; off >>= 1) {
            float ov = __shfl_down_sync(0xffffffffu, bv, off);
            int   oi = __shfl_down_sync(0xffffffffu, bi, off);
            if (ov < bv || (ov == bv && oi < bi)) { bv = ov; bi = oi; }
        }
        if (lane == 0) { sh.wv[w] = bv; sh.wi[w] = bi; }
        __syncthreads();
        if (w == 0) {
            bv = (lane < 8) ? sh.wv[lane] : 1e30f;
            bi = (lane < 8) ? sh.wi[lane] : 0x7fffffff;
            #pragma unroll
            for (int off = 4; off; off >>= 1) {
                float ov = __shfl_down_sync(0xffffffffu, bv, off);
                int   oi = __shfl_down_sync(0xffffffffu, bi, off);
                if (ov < bv || (ov == bv && oi < bi)) { bv = ov; bi = oi; }
            }
            if (lane == 0) { knn[bs*K_ + i] = base + bi; sh.win = bi; }
        }
        __syncthreads();
        int win = sh.win;
        #pragma unroll
        for (int p = 0; p < P; p++)
            if (win == t*P + p) pd[p] = 1e30f;
        __syncthreads();
    }
}

// ------------------- phase kernels -------------------------------------------
__global__ void k_nop() {}

// phase2: FPS0 (blocks 0..15) || stage2 GEMM (blocks 16..527)
__global__ void __launch_bounds__(256) k_phase2(const float* __restrict__ g1,
                                                const float* __restrict__ b1) {
    __shared__ Ph2U sh;
    if (blockIdx.x < 16)
        dev_fps<N_, S0_, 8>(sh.f, blockIdx.x, g_coords, g_fps0, g_xyz1);
    else
        dev_gemm(sh.g, blockIdx.x - 16, 0, g_h, g_w2t, g_h, 0, 64, 64, 0, g1, b1, 128);
}

// phase3: FPS1 [0,16) || P0 GEMM [16,1040) || tc0 GEMM [1040,1168) || kNN0 [1168,5264)
__global__ void __launch_bounds__(256) k_phase3(const float* __restrict__ g2,
                                                const float* __restrict__ b2) {
    __shared__ Ph3U sh;
    int bi = blockIdx.x;
    if (bi < 16) {
        dev_fps<S0_, S1_, 1>(sh.f, bi, g_xyz1, g_fps1, g_xyz2);
    } else if (bi < 1040) {
        int i = bi - 16;
        dev_gemm(sh.g, i & 511, i >> 9, g_h, g_wl0t, g_P, 0, 64, 128, 128, g2, b2, -1);
    } else if (bi < 1168) {
        int i = bi - 1040;
        dev_gemm(sh.g, i & 63, i >> 6, g_h, g_wd0t, g_tc, g_fps0, 64, 128, 128, g2, b2, -1);
    } else {
        dev_knn<N_, S0_, 8>(sh.k, bi - 1168, g_xyz1, g_coords, g_knn0);
    }
}

// phase4: kNN1 [0,2048) || group0 [2048,4096) (2 centroids per block)
__global__ void __launch_bounds__(256) k_phase4() {
    __shared__ Ph4U sh;
    int bi = blockIdx.x;
    if (bi < 2048) {
        dev_knn<S0_, S1_, 1>(sh.k, bi, g_xyz2, g_xyz1, g_knn1);
    } else {
        int blk = bi - 2048;
        int t = threadIdx.x;
        int half = t >> 7, o = t & 127;
        int bs = blk*2 + half;
        if (o < K_) sh.grp.idx[half][o] = g_knn0[bs*K_ + o];
        __syncthreads();
        float tcv = g_tc[bs*128 + o];
        float s = 0.f, q = 0.f, mx = -1e30f, mn = 1e30f;
        #pragma unroll 8
        for (int k = 0; k < K_; k++) {
            float v = g_P[sh.grp.idx[half][k]*128 + o] + tcv;
            s += v; q += v*v; mx = fmaxf(mx, v); mn = fminf(mn, v);
        }
        g_hmax[bs*128 + o] = mx;
        g_hmin[bs*128 + o] = mn;
        atomicAdd(&g_stats[256 + o], s);
        atomicAdd(&g_stats[256 + 128 + o], q);
    }
}

// phase6: P1 GEMM [0,256) || tc1 GEMM [256,384)
__global__ void __launch_bounds__(256) k_phase6() {
    __shared__ GemmS sh;
    int bi = blockIdx.x;
    if (bi < 256)
        dev_gemm(sh, bi & 63, bi >> 6, g_f1, g_wl1t, g_P, 0, 128, 256, -1, 0, 0, -1);
    else {
        int i = bi - 256;
        dev_gemm(sh, i & 31, i >> 5, g_f1, g_wd1t, g_tc, g_fps1, 128, 256, -1, 0, 0, -1);
    }
}

// group1: O=256, 1 centroid per block
__global__ void k_group1() {
    __shared__ int sidx[K_];
    int bs = blockIdx.x, o = threadIdx.x;
    if (o < K_) sidx[o] = g_knn1[bs*K_ + o];
    __syncthreads();
    float tcv = g_tc[bs*256 + o];
    float s = 0.f, q = 0.f, mx = -1e30f, mn = 1e30f;
    #pragma unroll 8
    for (int k = 0; k < K_; k++) {
        float v = g_P[sidx[k]*256 + o] + tcv;
        s += v; q += v*v; mx = fmaxf(mx, v); mn = fminf(mn, v);
    }
    g_hmax[bs*256 + o] = mx;
    g_hmin[bs*256 + o] = mn;
    atomicAdd(&g_stats[512 + o], s);
    atomicAdd(&g_stats[512 + 256 + o], q);
}

// finalize: BN + ReLU + (monotone) max over k
__global__ void k_finalize(const float* __restrict__ gamma, const float* __restrict__ beta,
                           int statsOff, int O, int S, float inv,
                           float* __restrict__ outp, int transposed) {
    int i = blockIdx.x * 256 + threadIdx.x;
    int o = i & (O - 1);
    float m   = g_stats[statsOff + o] * inv;
    float var = g_stats[statsOff + O + o] * inv - m*m;
    float sc  = gamma[o] * rsqrtf(var + EPS_);
    float h   = (sc >= 0.f) ? g_hmax[i] : g_hmin[i];
    float v   = fmaxf(0.f, (h - m) * sc + beta[o]);
    if (transposed) {
        int bs = i / O;
        int b = bs / S, ss = bs - b*S;
        outp[(b*O + o)*S + ss] = v;
    } else {
        g_f1[i] = v;
    }
}

// ------------------- launch ---------------------------------------------------
extern "C" void kernel_launch(void* const* d_in, const int* in_sizes, int n_in,
                              void* d_out, int out_size) {
    (void)in_sizes; (void)n_in; (void)out_size;
    const float* x    = (const float*)d_in[0];
    const float* w1   = (const float*)d_in[1];
    const float* g1   = (const float*)d_in[2];
    const float* b1   = (const float*)d_in[3];
    const float* w2   = (const float*)d_in[4];
    const float* g2   = (const float*)d_in[5];
    const float* b2   = (const float*)d_in[6];
    const float* wsg0 = (const float*)d_in[7];
    const float* gsg0 = (const float*)d_in[8];
    const float* bsg0 = (const float*)d_in[9];
    const float* wsg1 = (const float*)d_in[10];
    const float* gsg1 = (const float*)d_in[11];
    const float* bsg1 = (const float*)d_in[12];
    float* out = (float*)d_out;

    k_prepwA<<<20, 256>>>(w2);                                         // 1
    k_prepwB<<<320, 256>>>(wsg0, wsg1);                                // 2
    k_stage1<<<1024, 256>>>(x, w1);                                    // 3
    k_phase2<<<528, 256>>>(g1, b1);                                    // 4: fps0 || stage2 gemm
    k_nop<<<1, 32>>>();                                                // 5: shift ncu slot
    k_phase3<<<5264, 256>>>(g2, b2);                                   // 6: fps1 || P0 || tc0 || knn0 (profiled)
    k_phase4<<<4096, 256>>>();                                         // 7: knn1 || group0
    k_finalize<<<2048, 256>>>(gsg0, bsg0, 256, 128, S0_, 1.f/131072.f, out, 0);  // 8 -> f1
    k_phase6<<<384, 256>>>();                                          // 9: P1 || tc1
    k_group1<<<2048, 256>>>();                                         // 10
    k_finalize<<<2048, 256>>>(gsg1, bsg1, 512, 256, S1_, 1.f/65536.f, out, 1);   // 11
}